// round 13
// baseline (speedup 1.0000x reference)
#include <cuda_runtime.h>
#include <cuda_fp16.h>
#include <math.h>
#include <stdint.h>

#define BATCH 32768
#define HID   512
#define T_HIST 50
#define BJ 16            // hidden cols per gate per CTA
#define KC 16            // K chunk (one mma k16)
#define PS 24            // padded smem row stride (halfs) -> conflict-free ldsm
#define NST 3            // pipeline stages
#define NCH (HID / KC)   // 32

typedef __half h16;

// ---------------- device-global scratch (allocation-free) ----------------
__device__ h16 g_h0[2][(size_t)BATCH * HID];
__device__ h16 g_h1[2][(size_t)BATCH * HID];
#define WELEMS ((size_t)3 * HID * HID)
// [0]=enc_hh0 [1]=enc_ih1 [2]=enc_hh1 [3]=dec_hh0 [4]=dec_ih1 [5]=dec_hh1
__device__ h16 g_w[6][WELEMS];

// ---------------- helpers ----------------
__device__ __forceinline__ float sigmoidf_(float x) { return 1.0f / (1.0f + __expf(-x)); }
__device__ __forceinline__ float tanhf_(float x) {
    x = fminf(15.0f, fmaxf(-15.0f, x));
    float e = __expf(2.0f * x);
    return (e - 1.0f) / (e + 1.0f);
}
__device__ __forceinline__ uint32_t smem_u32(const void* p) {
    return (uint32_t)__cvta_generic_to_shared(p);
}
__device__ __forceinline__ void cp16(uint32_t dst, const void* src) {
    asm volatile("cp.async.cg.shared.global [%0], [%1], 16;" :: "r"(dst), "l"(src));
}
__device__ __forceinline__ void cp_commit() { asm volatile("cp.async.commit_group;"); }
__device__ __forceinline__ void ldsm4(uint32_t& r0, uint32_t& r1, uint32_t& r2, uint32_t& r3, uint32_t addr) {
    asm volatile("ldmatrix.sync.aligned.m8n8.x4.shared.b16 {%0,%1,%2,%3}, [%4];"
                 : "=r"(r0), "=r"(r1), "=r"(r2), "=r"(r3) : "r"(addr));
}
__device__ __forceinline__ void mma16816(float* c, const uint32_t* a, const uint32_t* b) {
    asm volatile("mma.sync.aligned.m16n8k16.row.col.f32.f16.f16.f32 "
                 "{%0,%1,%2,%3}, {%4,%5,%6,%7}, {%8,%9}, {%0,%1,%2,%3};"
                 : "+f"(c[0]), "+f"(c[1]), "+f"(c[2]), "+f"(c[3])
                 : "r"(a[0]), "r"(a[1]), "r"(a[2]), "r"(a[3]), "r"(b[0]), "r"(b[1]));
}

// ---------------- setup kernels ----------------
__global__ void prep_kernel(const float* w0, const float* w1, const float* w2,
                            const float* w3, const float* w4, const float* w5) {
    const float* srcs[6] = {w0, w1, w2, w3, w4, w5};
    size_t total = 6 * WELEMS;
    for (size_t i = (size_t)blockIdx.x * blockDim.x + threadIdx.x; i < total;
         i += (size_t)gridDim.x * blockDim.x) {
        int m = (int)(i / WELEMS);
        size_t e = i % WELEMS;
        g_w[m][e] = __float2half(srcs[m][e]);
    }
}

__global__ void zero_kernel() {
    size_t n = (size_t)BATCH * HID;
    h16 z = __float2half(0.0f);
    for (size_t i = (size_t)blockIdx.x * blockDim.x + threadIdx.x; i < n;
         i += (size_t)gridDim.x * blockDim.x) {
        g_h0[0][i] = z;
        g_h1[0][i] = z;
    }
}

// ---------------- fused GRU cell on fp16 mma.sync ----------------
// WITHX=true : 8 warps, 2 groups of 4; group0: W_hh x h, group1: W_ih x x.
//              BM = 128; smem exchange of ih gate pre-activations.
// WITHX=false: 8 warps, single group, Mw=32 -> BM = 256; W_ih0 (D=3) in fp32 epilogue.
// __launch_bounds__(256, 3): cap regs at 85 -> 3 CTAs/SM (24 warps).
template <bool WITHX>
__global__ void __launch_bounds__(256, 3)
gru_mma_kernel(const h16* __restrict__ x16,
               const float* __restrict__ x3, int x3_stride,
               const h16* __restrict__ h_in,
               const h16* __restrict__ wih, const float* __restrict__ wih3,
               const h16* __restrict__ whh,
               const float* __restrict__ b_ih, const float* __restrict__ b_hh,
               h16* __restrict__ h_out)
{
    extern __shared__ h16 smem[];
    constexpr int BM   = WITHX ? 128 : 256;
    constexpr int AROWS = WITHX ? 128 : 256;     // rows per A plane
    constexpr int NA   = WITHX ? 2 : 1;
    constexpr int NW   = WITHX ? 2 : 1;
    constexpr int APL  = AROWS * PS;             // halfs per A plane
    constexpr int AOFF = NA * APL;               // == 6144 both cases
    constexpr int WPL  = 48 * PS;                // 3 gates x 16 rows
    constexpr int STAGE = AOFF + NW * WPL;       // halfs
    constexpr int EXS = 17;                      // exchange row stride (floats)

    const int tid  = threadIdx.x;
    const int lane = tid & 31;
    const int warp = tid >> 5;
    const int grp  = WITHX ? (warp >> 2) : 0;
    const int wig  = WITHX ? (warp & 3) : warp;   // warp-in-group: rows wig*32..+31
    const int j0 = blockIdx.x * BJ;
    const int b0 = blockIdx.y * BM;
    const int gid = lane >> 2, tig = lane & 3;

    const h16* gA[2] = { h_in, x16 };
    const h16* gW[2] = { whh, wih };

    float acc[3][2][2][4];   // [gate][m-frag][nb][c]
#pragma unroll
    for (int g = 0; g < 3; g++)
#pragma unroll
        for (int m = 0; m < 2; m++)
#pragma unroll
            for (int nb = 0; nb < 2; nb++)
#pragma unroll
                for (int k = 0; k < 4; k++) acc[g][m][nb][k] = 0.0f;

    auto load_stage = [&](int slot, int c) {
        h16* st = smem + slot * STAGE;
        const int k0 = c * KC;
        // A planes: NA * AROWS rows * 2 segs of 16B  (= 512 cp16 both cases)
#pragma unroll
        for (int i = tid; i < NA * AROWS * 2; i += 256) {
            int pl  = WITHX ? (i >> 8) : 0;
            int rem = WITHX ? (i & 255) : i;
            int row = rem >> 1, seg = rem & 1;
            cp16(smem_u32(st + pl * APL + row * PS + seg * 8),
                 gA[pl] + (size_t)(b0 + row) * HID + k0 + seg * 8);
        }
        // W planes: NW * 48 rows * 2 segs
        {
            int i = tid;
            if (i < NW * 96) {
                int pl = i / 96, rem = i % 96;
                int row = rem >> 1, seg = rem & 1;
                int g = row >> 4, jj = row & 15;
                cp16(smem_u32(st + AOFF + pl * WPL + row * PS + seg * 8),
                     gW[pl] + (size_t)(g * HID + j0 + jj) * HID + k0 + seg * 8);
            }
        }
        cp_commit();
    };

    auto compute = [&](int slot) {
        h16* st = smem + slot * STAGE;
        // A fragments: 2 x m16k16 (rows wig*32 .. +31) from this group's plane
        uint32_t Af[2][4];
        const int a_row = lane & 15;
        const int a_col = (lane >> 4) * 8;
#pragma unroll
        for (int m = 0; m < 2; m++) {
            uint32_t addr = smem_u32(st + grp * APL + (wig * 32 + m * 16 + a_row) * PS + a_col);
            ldsm4(Af[m][0], Af[m][1], Af[m][2], Af[m][3], addr);
        }
        const int q = lane >> 3, mr = lane & 7;
#pragma unroll
        for (int g = 0; g < 3; g++) {
            uint32_t Bf[2][2];
            h16* base = st + AOFF + grp * WPL + (g * 16) * PS;
            uint32_t addr = smem_u32(base + ((q >> 1) * 8 + mr) * PS + (q & 1) * 8);
            ldsm4(Bf[0][0], Bf[0][1], Bf[1][0], Bf[1][1], addr);
#pragma unroll
            for (int m = 0; m < 2; m++)
#pragma unroll
                for (int nb = 0; nb < 2; nb++)
                    mma16816(acc[g][m][nb], Af[m], Bf[nb]);
        }
    };

    // ---- 3-stage pipeline, one sync per chunk ----
    load_stage(0, 0);
    load_stage(1, 1);
    for (int c = 0; c < NCH; c++) {
        if (c + 1 < NCH) asm volatile("cp.async.wait_group 1;");
        else             asm volatile("cp.async.wait_group 0;");
        __syncthreads();
        if (c + 2 < NCH) load_stage((c + 2) % NST, c + 2);
        compute(c % NST);
    }

    // ---- epilogue ----
    float* exch = (float*)smem;       // overlay on dead pipeline stages
    __syncthreads();                  // everyone done reading smem

    if (WITHX && grp == 1) {
        // publish ih gate pre-activations
#pragma unroll
        for (int m = 0; m < 2; m++)
#pragma unroll
            for (int h8 = 0; h8 < 2; h8++) {
                const int row = wig * 32 + m * 16 + gid + h8 * 8;
#pragma unroll
                for (int nb = 0; nb < 2; nb++)
#pragma unroll
                    for (int cc = 0; cc < 2; cc++) {
                        const int col = nb * 8 + tig * 2 + cc;
#pragma unroll
                        for (int g = 0; g < 3; g++)
                            exch[(g * 128 + row) * EXS + col] = acc[g][m][nb][h8 * 2 + cc];
                    }
            }
    }
    if (WITHX) __syncthreads();

    if (grp == 0) {
#pragma unroll
        for (int m = 0; m < 2; m++)
#pragma unroll
            for (int h8 = 0; h8 < 2; h8++) {
                const int row = wig * 32 + m * 16 + gid + h8 * 8;
                const int b = b0 + row;
                float x0f = 0.f, x1f = 0.f, x2f = 0.f;
                if (!WITHX) {
                    x0f = x3[(size_t)b * x3_stride + 0];
                    x1f = x3[(size_t)b * x3_stride + 1];
                    x2f = x3[(size_t)b * x3_stride + 2];
                }
#pragma unroll
                for (int nb = 0; nb < 2; nb++) {
                    const int j = j0 + nb * 8 + tig * 2;      // pair (j, j+1)
                    const size_t idx = (size_t)b * HID + j;
                    __half2 hp2 = *(const __half2*)(h_in + idx);
                    float hnew[2];
#pragma unroll
                    for (int cc = 0; cc < 2; cc++) {
                        const int jj = j + cc;
                        const int fi = h8 * 2 + cc;
                        float hr = acc[0][m][nb][fi] + b_hh[jj];
                        float hz = acc[1][m][nb][fi] + b_hh[HID + jj];
                        float hn = acc[2][m][nb][fi] + b_hh[2 * HID + jj];
                        float ir, iz, in_;
                        if (WITHX) {
                            const int col = nb * 8 + tig * 2 + cc;
                            ir  = exch[(0 * 128 + row) * EXS + col] + b_ih[jj];
                            iz  = exch[(1 * 128 + row) * EXS + col] + b_ih[HID + jj];
                            in_ = exch[(2 * 128 + row) * EXS + col] + b_ih[2 * HID + jj];
                        } else {
                            const float* w0 = &wih3[(size_t)jj * 3];
                            const float* w1 = &wih3[(size_t)(HID + jj) * 3];
                            const float* w2 = &wih3[(size_t)(2 * HID + jj) * 3];
                            ir  = x0f * w0[0] + x1f * w0[1] + x2f * w0[2] + b_ih[jj];
                            iz  = x0f * w1[0] + x1f * w1[1] + x2f * w1[2] + b_ih[HID + jj];
                            in_ = x0f * w2[0] + x1f * w2[1] + x2f * w2[2] + b_ih[2 * HID + jj];
                        }
                        float r = sigmoidf_(ir + hr);
                        float z = sigmoidf_(iz + hz);
                        float n = tanhf_(in_ + r * hn);
                        float hp = __half2float(cc == 0 ? __low2half(hp2) : __high2half(hp2));
                        hnew[cc] = (1.0f - z) * n + z * hp;
                    }
                    *(__half2*)(h_out + idx) = __floats2half2_rn(hnew[0], hnew[1]);
                }
            }
    }
}

// ---------------- output head ----------------
__global__ void fc_kernel(const h16* __restrict__ h,
                          const float* __restrict__ fc_W, const float* __restrict__ fc_b,
                          float* __restrict__ out, int out_stride)
{
    int warp = (blockIdx.x * blockDim.x + threadIdx.x) >> 5;
    int lane = threadIdx.x & 31;
    if (warp >= BATCH) return;
    float a0 = 0.f, a1 = 0.f, a2 = 0.f;
    for (int k = lane; k < HID; k += 32) {
        float hv = __half2float(h[(size_t)warp * HID + k]);
        a0 += hv * fc_W[k];
        a1 += hv * fc_W[HID + k];
        a2 += hv * fc_W[2 * HID + k];
    }
#pragma unroll
    for (int off = 16; off > 0; off >>= 1) {
        a0 += __shfl_down_sync(0xffffffffu, a0, off);
        a1 += __shfl_down_sync(0xffffffffu, a1, off);
        a2 += __shfl_down_sync(0xffffffffu, a2, off);
    }
    if (lane == 0) {
        float* o = &out[(size_t)warp * out_stride];
        o[0] = a0 + fc_b[0];
        o[1] = a1 + fc_b[1];
        o[2] = a2 + fc_b[2];
    }
}

// ---------------- launcher ----------------
extern "C" void kernel_launch(void* const* d_in, const int* in_sizes, int n_in,
                              void* d_out, int out_size)
{
    const float* x_input   = (const float*)d_in[0];
    const float* enc_W_ih0 = (const float*)d_in[2];
    const float* enc_W_hh0 = (const float*)d_in[3];
    const float* enc_b_ih0 = (const float*)d_in[4];
    const float* enc_b_hh0 = (const float*)d_in[5];
    const float* enc_W_ih1 = (const float*)d_in[6];
    const float* enc_W_hh1 = (const float*)d_in[7];
    const float* enc_b_ih1 = (const float*)d_in[8];
    const float* enc_b_hh1 = (const float*)d_in[9];
    const float* dec_W_ih0 = (const float*)d_in[10];
    const float* dec_W_hh0 = (const float*)d_in[11];
    const float* dec_b_ih0 = (const float*)d_in[12];
    const float* dec_b_hh0 = (const float*)d_in[13];
    const float* dec_W_ih1 = (const float*)d_in[14];
    const float* dec_W_hh1 = (const float*)d_in[15];
    const float* dec_b_ih1 = (const float*)d_in[16];
    const float* dec_b_hh1 = (const float*)d_in[17];
    const float* fc_W      = (const float*)d_in[18];
    const float* fc_b      = (const float*)d_in[19];
    float* out = (float*)d_out;

    const int F = out_size / (BATCH * 3);

    // stage sizes in halfs -> bytes
    const int stage1 = (2 * 128 * PS + 2 * 48 * PS) * (int)sizeof(h16);  // 16896 B
    const int stage0 = (1 * 256 * PS + 1 * 48 * PS) * (int)sizeof(h16);  // 14592 B
    cudaFuncSetAttribute(gru_mma_kernel<true>,  cudaFuncAttributeMaxDynamicSharedMemorySize, NST * stage1);
    cudaFuncSetAttribute(gru_mma_kernel<false>, cudaFuncAttributeMaxDynamicSharedMemorySize, NST * stage0);

    h16 *h0_b, *h1_b, *w_b;
    cudaGetSymbolAddress((void**)&h0_b, g_h0);
    cudaGetSymbolAddress((void**)&h1_b, g_h1);
    cudaGetSymbolAddress((void**)&w_b,  g_w);
    const size_t HN = (size_t)BATCH * HID;
    h16* h0[2] = { h0_b, h0_b + HN };
    h16* h1[2] = { h1_b, h1_b + HN };
    auto W = [&](int m) { return w_b + (size_t)m * WELEMS; };

    prep_kernel<<<2048, 256>>>(enc_W_hh0, enc_W_ih1, enc_W_hh1,
                               dec_W_hh0, dec_W_ih1, dec_W_hh1);
    zero_kernel<<<2048, 256>>>();

    dim3 grid1(HID / BJ, BATCH / 128);   // (32, 256)
    dim3 grid0(HID / BJ, BATCH / 256);   // (32, 128)
    int p0 = 0, p1 = 0;

    // ---- encoder ----
    for (int t = 0; t < T_HIST; t++) {
        gru_mma_kernel<false><<<grid0, 256, NST * stage0>>>(
            nullptr, x_input + t * 3, T_HIST * 3,
            h0[p0],
            nullptr, enc_W_ih0,
            W(0),
            enc_b_ih0, enc_b_hh0,
            h0[p0 ^ 1]);
        p0 ^= 1;
        gru_mma_kernel<true><<<grid1, 256, NST * stage1>>>(
            h0[p0], nullptr, 0,
            h1[p1],
            W(1), nullptr,
            W(2),
            enc_b_ih1, enc_b_hh1,
            h1[p1 ^ 1]);
        p1 ^= 1;
    }

    // ---- decoder ----
    for (int t = 0; t < F; t++) {
        const float* xin = (t == 0) ? (x_input + (T_HIST - 1) * 3) : (out + (t - 1) * 3);
        int xs = (t == 0) ? (T_HIST * 3) : (F * 3);
        gru_mma_kernel<false><<<grid0, 256, NST * stage0>>>(
            nullptr, xin, xs,
            h0[p0],
            nullptr, dec_W_ih0,
            W(3),
            dec_b_ih0, dec_b_hh0,
            h0[p0 ^ 1]);
        p0 ^= 1;
        gru_mma_kernel<true><<<grid1, 256, NST * stage1>>>(
            h0[p0], nullptr, 0,
            h1[p1],
            W(4), nullptr,
            W(5),
            dec_b_ih1, dec_b_hh1,
            h1[p1 ^ 1]);
        p1 ^= 1;
        fc_kernel<<<(BATCH * 32) / 256, 256>>>(h1[p1], fc_W, fc_b, out + t * 3, F * 3);
    }
}

// round 15
// speedup vs baseline: 1.2511x; 1.2511x over previous
#include <cuda_runtime.h>
#include <cuda_fp16.h>
#include <math.h>
#include <stdint.h>

#define BATCH 32768
#define HID   512
#define T_HIST 50
#define BJ 32            // hidden cols per gate per CTA
#define KC 32            // K chunk (two mma k16 sub-blocks)
#define PS 40            // padded smem row stride (halfs) -> conflict-free ldsm
#define NST 2            // pipeline stages
#define NCH (HID / KC)   // 16

typedef __half h16;

// ---------------- device-global scratch (allocation-free) ----------------
__device__ h16 g_h0[2][(size_t)BATCH * HID];
__device__ h16 g_h1[2][(size_t)BATCH * HID];
#define WELEMS ((size_t)3 * HID * HID)
// [0]=enc_hh0 [1]=enc_ih1 [2]=enc_hh1 [3]=dec_hh0 [4]=dec_ih1 [5]=dec_hh1
__device__ h16 g_w[6][WELEMS];

// ---------------- helpers ----------------
__device__ __forceinline__ float sigmoidf_(float x) { return 1.0f / (1.0f + __expf(-x)); }
__device__ __forceinline__ float tanhf_(float x) {
    x = fminf(15.0f, fmaxf(-15.0f, x));
    float e = __expf(2.0f * x);
    return (e - 1.0f) / (e + 1.0f);
}
__device__ __forceinline__ uint32_t smem_u32(const void* p) {
    return (uint32_t)__cvta_generic_to_shared(p);
}
__device__ __forceinline__ void cp16(uint32_t dst, const void* src) {
    asm volatile("cp.async.cg.shared.global [%0], [%1], 16;" :: "r"(dst), "l"(src));
}
__device__ __forceinline__ void cp_commit() { asm volatile("cp.async.commit_group;"); }
__device__ __forceinline__ void ldsm4(uint32_t& r0, uint32_t& r1, uint32_t& r2, uint32_t& r3, uint32_t addr) {
    asm volatile("ldmatrix.sync.aligned.m8n8.x4.shared.b16 {%0,%1,%2,%3}, [%4];"
                 : "=r"(r0), "=r"(r1), "=r"(r2), "=r"(r3) : "r"(addr));
}
__device__ __forceinline__ void mma16816(float* c, const uint32_t* a, const uint32_t* b) {
    asm volatile("mma.sync.aligned.m16n8k16.row.col.f32.f16.f16.f32 "
                 "{%0,%1,%2,%3}, {%4,%5,%6,%7}, {%8,%9}, {%0,%1,%2,%3};"
                 : "+f"(c[0]), "+f"(c[1]), "+f"(c[2]), "+f"(c[3])
                 : "r"(a[0]), "r"(a[1]), "r"(a[2]), "r"(a[3]), "r"(b[0]), "r"(b[1]));
}

// ---------------- setup kernels ----------------
__global__ void prep_kernel(const float* w0, const float* w1, const float* w2,
                            const float* w3, const float* w4, const float* w5) {
    const float* srcs[6] = {w0, w1, w2, w3, w4, w5};
    size_t total = 6 * WELEMS;
    for (size_t i = (size_t)blockIdx.x * blockDim.x + threadIdx.x; i < total;
         i += (size_t)gridDim.x * blockDim.x) {
        int m = (int)(i / WELEMS);
        size_t e = i % WELEMS;
        g_w[m][e] = __float2half(srcs[m][e]);
    }
}

__global__ void zero_kernel() {
    size_t n = (size_t)BATCH * HID;
    h16 z = __float2half(0.0f);
    for (size_t i = (size_t)blockIdx.x * blockDim.x + threadIdx.x; i < n;
         i += (size_t)gridDim.x * blockDim.x) {
        g_h0[0][i] = z;
        g_h1[0][i] = z;
    }
}

// ---------------- fused GRU cell on fp16 mma.sync ----------------
// WITHX=true : 8 warps, 2 groups of 4; group0: W_hh x h, group1: W_ih x x.
//              BM = 128; smem exchange of ih gate pre-activations.
// WITHX=false: 8 warps, single group, Mw=32 -> BM = 256; W_ih0 (D=3) in fp32 epilogue.
// __launch_bounds__(256, 2): cap regs at 128 -> 2 CTAs/SM.
template <bool WITHX>
__global__ void __launch_bounds__(256, 2)
gru_mma_kernel(const h16* __restrict__ x16,
               const float* __restrict__ x3, int x3_stride,
               const h16* __restrict__ h_in,
               const h16* __restrict__ wih, const float* __restrict__ wih3,
               const h16* __restrict__ whh,
               const float* __restrict__ b_ih, const float* __restrict__ b_hh,
               h16* __restrict__ h_out)
{
    extern __shared__ h16 smem[];
    constexpr int BM    = WITHX ? 128 : 256;
    constexpr int AROWS = WITHX ? 128 : 256;     // rows per A plane
    constexpr int NA    = WITHX ? 2 : 1;
    constexpr int NW    = WITHX ? 2 : 1;
    constexpr int APL   = AROWS * PS;            // halfs per A plane
    constexpr int AOFF  = NA * APL;              // == 10240 halfs both cases
    constexpr int WPL   = 96 * PS;
    constexpr int STAGE = AOFF + NW * WPL;       // halfs
    constexpr int EXS   = 33;                    // exchange row stride (floats)

    const int tid  = threadIdx.x;
    const int lane = tid & 31;
    const int warp = tid >> 5;
    const int grp  = WITHX ? (warp >> 2) : 0;
    const int wig  = WITHX ? (warp & 3) : warp;   // warp-in-group: rows wig*32..+31
    const int j0 = blockIdx.x * BJ;
    const int b0 = blockIdx.y * BM;
    const int gid = lane >> 2, tig = lane & 3;

    const h16* gA[2] = { h_in, x16 };
    const h16* gW[2] = { whh, wih };

    float acc[3][2][4][4];   // [gate][m-frag][nb][c]
#pragma unroll
    for (int g = 0; g < 3; g++)
#pragma unroll
        for (int m = 0; m < 2; m++)
#pragma unroll
            for (int nb = 0; nb < 4; nb++)
#pragma unroll
                for (int k = 0; k < 4; k++) acc[g][m][nb][k] = 0.0f;

    auto load_stage = [&](int slot, int c) {
        h16* st = smem + slot * STAGE;
        const int k0 = c * KC;
        // A planes: NA * AROWS rows * 4 segs of 16B
#pragma unroll
        for (int i = tid; i < NA * AROWS * 4; i += 256) {
            int pl  = WITHX ? (i >> 9) : 0;
            int rem = WITHX ? (i & 511) : i;
            int row = rem >> 2, seg = rem & 3;
            cp16(smem_u32(st + pl * APL + row * PS + seg * 8),
                 gA[pl] + (size_t)(b0 + row) * HID + k0 + seg * 8);
        }
        // W planes: NW * 96 rows * 4 segs
#pragma unroll
        for (int i = tid; i < NW * 384; i += 256) {
            int pl = i / 384, rem = i % 384;
            int row = rem >> 2, seg = rem & 3;
            int g = row >> 5, jj = row & 31;
            cp16(smem_u32(st + AOFF + pl * WPL + row * PS + seg * 8),
                 gW[pl] + (size_t)(g * HID + j0 + jj) * HID + k0 + seg * 8);
        }
        cp_commit();
    };

    auto compute = [&](int slot) {
        h16* st = smem + slot * STAGE;
        const int a_row = lane & 15;
        const int a_col = (lane >> 4) * 8;
        const int q = lane >> 3, mr = lane & 7;
        // two k16 sub-blocks, processed sequentially (keeps live regs low)
#pragma unroll
        for (int ks = 0; ks < 2; ks++) {
            const int kofs = ks * 16;
            uint32_t Af[2][4];
#pragma unroll
            for (int m = 0; m < 2; m++) {
                uint32_t addr = smem_u32(st + grp * APL + (wig * 32 + m * 16 + a_row) * PS + kofs + a_col);
                ldsm4(Af[m][0], Af[m][1], Af[m][2], Af[m][3], addr);
            }
#pragma unroll
            for (int g = 0; g < 3; g++) {
                uint32_t Bf[4][2];
                h16* base = st + AOFF + grp * WPL + (g * 32) * PS + kofs;
#pragma unroll
                for (int half = 0; half < 2; half++) {
                    uint32_t addr = smem_u32(base + (half * 16 + (q >> 1) * 8 + mr) * PS + (q & 1) * 8);
                    ldsm4(Bf[half * 2][0], Bf[half * 2][1],
                          Bf[half * 2 + 1][0], Bf[half * 2 + 1][1], addr);
                }
#pragma unroll
                for (int m = 0; m < 2; m++)
#pragma unroll
                    for (int nb = 0; nb < 4; nb++)
                        mma16816(acc[g][m][nb], Af[m], Bf[nb]);
            }
        }
    };

    // ---- 2-stage pipeline, one sync per 32-wide chunk ----
    load_stage(0, 0);
    for (int c = 0; c < NCH; c++) {
        if (c + 1 < NCH) {
            load_stage((c + 1) & 1, c + 1);
            asm volatile("cp.async.wait_group 1;");
        } else {
            asm volatile("cp.async.wait_group 0;");
        }
        __syncthreads();
        compute(c & 1);
        __syncthreads();
    }

    // ---- epilogue ----
    float* exch = (float*)smem;       // overlay on dead pipeline stages

    if (WITHX && grp == 1) {
        // publish ih gate pre-activations
#pragma unroll
        for (int m = 0; m < 2; m++)
#pragma unroll
            for (int h8 = 0; h8 < 2; h8++) {
                const int row = wig * 32 + m * 16 + gid + h8 * 8;
#pragma unroll
                for (int nb = 0; nb < 4; nb++)
#pragma unroll
                    for (int cc = 0; cc < 2; cc++) {
                        const int col = nb * 8 + tig * 2 + cc;
#pragma unroll
                        for (int g = 0; g < 3; g++)
                            exch[(g * 128 + row) * EXS + col] = acc[g][m][nb][h8 * 2 + cc];
                    }
            }
    }
    if (WITHX) __syncthreads();

    if (grp == 0) {
#pragma unroll
        for (int m = 0; m < 2; m++)
#pragma unroll
            for (int h8 = 0; h8 < 2; h8++) {
                const int row = wig * 32 + m * 16 + gid + h8 * 8;
                const int b = b0 + row;
                float x0f = 0.f, x1f = 0.f, x2f = 0.f;
                if (!WITHX) {
                    x0f = x3[(size_t)b * x3_stride + 0];
                    x1f = x3[(size_t)b * x3_stride + 1];
                    x2f = x3[(size_t)b * x3_stride + 2];
                }
#pragma unroll
                for (int nb = 0; nb < 4; nb++) {
                    const int j = j0 + nb * 8 + tig * 2;      // pair (j, j+1)
                    const size_t idx = (size_t)b * HID + j;
                    __half2 hp2 = *(const __half2*)(h_in + idx);
                    float hnew[2];
#pragma unroll
                    for (int cc = 0; cc < 2; cc++) {
                        const int jj = j + cc;
                        const int fi = h8 * 2 + cc;
                        float hr = acc[0][m][nb][fi] + b_hh[jj];
                        float hz = acc[1][m][nb][fi] + b_hh[HID + jj];
                        float hn = acc[2][m][nb][fi] + b_hh[2 * HID + jj];
                        float ir, iz, in_;
                        if (WITHX) {
                            const int col = nb * 8 + tig * 2 + cc;
                            ir  = exch[(0 * 128 + row) * EXS + col] + b_ih[jj];
                            iz  = exch[(1 * 128 + row) * EXS + col] + b_ih[HID + jj];
                            in_ = exch[(2 * 128 + row) * EXS + col] + b_ih[2 * HID + jj];
                        } else {
                            const float* w0 = &wih3[(size_t)jj * 3];
                            const float* w1 = &wih3[(size_t)(HID + jj) * 3];
                            const float* w2 = &wih3[(size_t)(2 * HID + jj) * 3];
                            ir  = x0f * w0[0] + x1f * w0[1] + x2f * w0[2] + b_ih[jj];
                            iz  = x0f * w1[0] + x1f * w1[1] + x2f * w1[2] + b_ih[HID + jj];
                            in_ = x0f * w2[0] + x1f * w2[1] + x2f * w2[2] + b_ih[2 * HID + jj];
                        }
                        float r = sigmoidf_(ir + hr);
                        float z = sigmoidf_(iz + hz);
                        float n = tanhf_(in_ + r * hn);
                        float hp = __half2float(cc == 0 ? __low2half(hp2) : __high2half(hp2));
                        hnew[cc] = (1.0f - z) * n + z * hp;
                    }
                    *(__half2*)(h_out + idx) = __floats2half2_rn(hnew[0], hnew[1]);
                }
            }
    }
}

// ---------------- output head ----------------
__global__ void fc_kernel(const h16* __restrict__ h,
                          const float* __restrict__ fc_W, const float* __restrict__ fc_b,
                          float* __restrict__ out, int out_stride)
{
    int warp = (blockIdx.x * blockDim.x + threadIdx.x) >> 5;
    int lane = threadIdx.x & 31;
    if (warp >= BATCH) return;
    float a0 = 0.f, a1 = 0.f, a2 = 0.f;
    for (int k = lane; k < HID; k += 32) {
        float hv = __half2float(h[(size_t)warp * HID + k]);
        a0 += hv * fc_W[k];
        a1 += hv * fc_W[HID + k];
        a2 += hv * fc_W[2 * HID + k];
    }
#pragma unroll
    for (int off = 16; off > 0; off >>= 1) {
        a0 += __shfl_down_sync(0xffffffffu, a0, off);
        a1 += __shfl_down_sync(0xffffffffu, a1, off);
        a2 += __shfl_down_sync(0xffffffffu, a2, off);
    }
    if (lane == 0) {
        float* o = &out[(size_t)warp * out_stride];
        o[0] = a0 + fc_b[0];
        o[1] = a1 + fc_b[1];
        o[2] = a2 + fc_b[2];
    }
}

// ---------------- launcher ----------------
extern "C" void kernel_launch(void* const* d_in, const int* in_sizes, int n_in,
                              void* d_out, int out_size)
{
    const float* x_input   = (const float*)d_in[0];
    const float* enc_W_ih0 = (const float*)d_in[2];
    const float* enc_W_hh0 = (const float*)d_in[3];
    const float* enc_b_ih0 = (const float*)d_in[4];
    const float* enc_b_hh0 = (const float*)d_in[5];
    const float* enc_W_ih1 = (const float*)d_in[6];
    const float* enc_W_hh1 = (const float*)d_in[7];
    const float* enc_b_ih1 = (const float*)d_in[8];
    const float* enc_b_hh1 = (const float*)d_in[9];
    const float* dec_W_ih0 = (const float*)d_in[10];
    const float* dec_W_hh0 = (const float*)d_in[11];
    const float* dec_b_ih0 = (const float*)d_in[12];
    const float* dec_b_hh0 = (const float*)d_in[13];
    const float* dec_W_ih1 = (const float*)d_in[14];
    const float* dec_W_hh1 = (const float*)d_in[15];
    const float* dec_b_ih1 = (const float*)d_in[16];
    const float* dec_b_hh1 = (const float*)d_in[17];
    const float* fc_W      = (const float*)d_in[18];
    const float* fc_b      = (const float*)d_in[19];
    float* out = (float*)d_out;

    const int F = out_size / (BATCH * 3);

    // stage sizes in halfs -> bytes
    const int stage1 = (2 * 128 * PS + 2 * 96 * PS) * (int)sizeof(h16);  // 35840 B
    const int stage0 = (1 * 256 * PS + 1 * 96 * PS) * (int)sizeof(h16);  // 28160 B
    cudaFuncSetAttribute(gru_mma_kernel<true>,  cudaFuncAttributeMaxDynamicSharedMemorySize, NST * stage1);
    cudaFuncSetAttribute(gru_mma_kernel<false>, cudaFuncAttributeMaxDynamicSharedMemorySize, NST * stage0);

    h16 *h0_b, *h1_b, *w_b;
    cudaGetSymbolAddress((void**)&h0_b, g_h0);
    cudaGetSymbolAddress((void**)&h1_b, g_h1);
    cudaGetSymbolAddress((void**)&w_b,  g_w);
    const size_t HN = (size_t)BATCH * HID;
    h16* h0[2] = { h0_b, h0_b + HN };
    h16* h1[2] = { h1_b, h1_b + HN };
    auto W = [&](int m) { return w_b + (size_t)m * WELEMS; };

    prep_kernel<<<2048, 256>>>(enc_W_hh0, enc_W_ih1, enc_W_hh1,
                               dec_W_hh0, dec_W_ih1, dec_W_hh1);
    zero_kernel<<<2048, 256>>>();

    dim3 grid1(HID / BJ, BATCH / 128);   // (16, 256)
    dim3 grid0(HID / BJ, BATCH / 256);   // (16, 128)
    int p0 = 0, p1 = 0;

    // ---- encoder ----
    for (int t = 0; t < T_HIST; t++) {
        gru_mma_kernel<false><<<grid0, 256, NST * stage0>>>(
            nullptr, x_input + t * 3, T_HIST * 3,
            h0[p0],
            nullptr, enc_W_ih0,
            W(0),
            enc_b_ih0, enc_b_hh0,
            h0[p0 ^ 1]);
        p0 ^= 1;
        gru_mma_kernel<true><<<grid1, 256, NST * stage1>>>(
            h0[p0], nullptr, 0,
            h1[p1],
            W(1), nullptr,
            W(2),
            enc_b_ih1, enc_b_hh1,
            h1[p1 ^ 1]);
        p1 ^= 1;
    }

    // ---- decoder ----
    for (int t = 0; t < F; t++) {
        const float* xin = (t == 0) ? (x_input + (T_HIST - 1) * 3) : (out + (t - 1) * 3);
        int xs = (t == 0) ? (T_HIST * 3) : (F * 3);
        gru_mma_kernel<false><<<grid0, 256, NST * stage0>>>(
            nullptr, xin, xs,
            h0[p0],
            nullptr, dec_W_ih0,
            W(3),
            dec_b_ih0, dec_b_hh0,
            h0[p0 ^ 1]);
        p0 ^= 1;
        gru_mma_kernel<true><<<grid1, 256, NST * stage1>>>(
            h0[p0], nullptr, 0,
            h1[p1],
            W(4), nullptr,
            W(5),
            dec_b_ih1, dec_b_hh1,
            h1[p1 ^ 1]);
        p1 ^= 1;
        fc_kernel<<<(BATCH * 32) / 256, 256>>>(h1[p1], fc_W, fc_b, out + t * 3, F * 3);
    }
}